// round 1
// baseline (speedup 1.0000x reference)
#include <cuda_runtime.h>
#include <math.h>

#define NN   10000
#define EE   160000
#define CC   64
#define SHD  9
#define NBS  8
#define MLPHD 16
#define RMAXF 5.0f

// ---------------- device scratch (static, allocation-free) ----------------
__device__ float d_sh[EE * SHD];        // spherical harmonics per active edge
__device__ float d_z[2][EE * 16];       // silu(radial @ W_r1[t]) per active edge
__device__ unsigned char d_act[EE];
__device__ int   d_count[NN];
__device__ int   d_offs[NN + 1];
__device__ int   d_cursor[NN];
__device__ int   d_sorted[EE];
__device__ float d_hA[NN * CC];
__device__ float d_hB[NN * CC];
__device__ float d_hup[NN * CC];
__device__ float d_agg[NN * CC * SHD];  // [n][c*9+s]

// ---------------- kernels ----------------
__global__ void k_zero_counts() {
    int i = blockIdx.x * blockDim.x + threadIdx.x;
    if (i < NN) d_count[i] = 0;
}

// h0 = node_attrs @ W_embed ; out[0][n] = node_attrs @ atomic_energies
__global__ void k_embed(const float* __restrict__ na, const float* __restrict__ We,
                        const float* __restrict__ ae, float* __restrict__ out) {
    int n = blockIdx.x;
    int c = threadIdx.x;
    float acc = 0.f;
#pragma unroll
    for (int k = 0; k < 10; k++) acc = fmaf(na[n * 10 + k], We[k * CC + c], acc);
    d_hA[n * CC + c] = acc;
    if (c == 0) {
        float r = 0.f;
#pragma unroll
        for (int k = 0; k < 10; k++) r = fmaf(na[n * 10 + k], ae[k], r);
        out[n] = r;
    }
}

// Per-edge geometry: sh[9], radial Bessel*cutoff, z[t][16]; histogram by rcv.
__global__ void k_geom(const float* __restrict__ pos, const float* __restrict__ shifts,
                       const int* __restrict__ ei, const float* __restrict__ Wr1) {
    int e = blockIdx.x * blockDim.x + threadIdx.x;
    if (e >= EE) return;
    int s  = ei[e];
    int rv = ei[EE + e];
    float vx = pos[rv * 3 + 0] - pos[s * 3 + 0] + shifts[e * 3 + 0];
    float vy = pos[rv * 3 + 1] - pos[s * 3 + 1] + shifts[e * 3 + 1];
    float vz = pos[rv * 3 + 2] - pos[s * 3 + 2] + shifts[e * 3 + 2];
    float r = sqrtf(vx * vx + vy * vy + vz * vz) + 1e-9f;
    float xx = r * (1.0f / RMAXF);
    bool act = (xx < 1.0f);
    d_act[e] = act ? 1 : 0;
    if (!act) return;             // fc == 0 -> exact-zero contribution
    atomicAdd(&d_count[rv], 1);

    float inv = 1.0f / r;
    float ux = vx * inv, uy = vy * inv, uz = vz * inv;
    const float s3 = 1.7320508075688772f, s5 = 2.2360679774997896f, s15 = 3.872983346207417f;
    float sh[9];
    sh[0] = 1.0f;
    sh[1] = s3 * ux;  sh[2] = s3 * uy;  sh[3] = s3 * uz;
    sh[4] = s15 * ux * uy; sh[5] = s15 * uy * uz;
    sh[6] = 0.5f * s5 * (3.0f * uz * uz - 1.0f);
    sh[7] = s15 * ux * uz;
    sh[8] = 0.5f * s15 * (ux * ux - uy * uy);
#pragma unroll
    for (int i = 0; i < 9; i++) d_sh[e * 9 + i] = sh[i];

    // Bessel basis via sin recurrence; cutoff polynomial p=6.
    float th = 3.14159265358979323846f * xx;
    float s1 = sinf(th), c1 = cosf(th);
    float x2 = xx * xx;
    float x6 = x2 * x2 * x2;
    float fc = 1.0f + x6 * (-28.0f + xx * (48.0f - 21.0f * xx));
    float pref = 0.6324555320336759f * inv * fc;   // sqrt(2/5)/r * fc
    float ef[8];
    float sp = 0.0f, sc = s1, c2 = 2.0f * c1;
#pragma unroll
    for (int n = 0; n < 8; n++) {
        ef[n] = pref * sc;
        float nx = c2 * sc - sp;
        sp = sc; sc = nx;
    }
#pragma unroll
    for (int t = 0; t < 2; t++) {
#pragma unroll
        for (int m = 0; m < 16; m++) {
            float a = 0.f;
#pragma unroll
            for (int n = 0; n < 8; n++) a = fmaf(ef[n], Wr1[t * 128 + n * 16 + m], a);
            d_z[t][e * 16 + m] = a / (1.0f + expf(-a));   // silu
        }
    }
}

// Exclusive scan over d_count (single block).
__global__ void k_scan() {
    const int CH = (NN + 1023) / 1024;   // 10
    __shared__ int shm[1024];
    int t = threadIdx.x;
    int base = t * CH;
    int s = 0;
    for (int i = 0; i < CH; i++) { int idx = base + i; if (idx < NN) s += d_count[idx]; }
    shm[t] = s;
    __syncthreads();
    for (int off = 1; off < 1024; off <<= 1) {
        int v = 0;
        if (t >= off) v = shm[t - off];
        __syncthreads();
        if (t >= off) shm[t] += v;
        __syncthreads();
    }
    int run = (t == 0) ? 0 : shm[t - 1];
    for (int i = 0; i < CH; i++) {
        int idx = base + i;
        if (idx < NN) { d_offs[idx] = run; d_cursor[idx] = run; run += d_count[idx]; }
    }
    if (t == 1023) d_offs[NN] = shm[1023];
}

__global__ void k_scatter(const int* __restrict__ ei) {
    int e = blockIdx.x * blockDim.x + threadIdx.x;
    if (e >= EE) return;
    if (!d_act[e]) return;
    int rv = ei[EE + e];
    int p = atomicAdd(&d_cursor[rv], 1);
    d_sorted[p] = e;
}

// h_up = h @ W_up[t]
__global__ __launch_bounds__(256) void k_hup(int hsel, const float* __restrict__ Wup) {
    const float* __restrict__ h = hsel ? d_hB : d_hA;
    __shared__ float Ws[CC * CC];
    __shared__ float hs[16 * CC];
    int tid = threadIdx.x;
    int base = blockIdx.x * 16;
#pragma unroll
    for (int i = 0; i < 16; i++) Ws[tid + i * 256] = Wup[tid + i * 256];
#pragma unroll
    for (int i = 0; i < 4; i++) {
        int lin = tid + i * 256;
        int ln = lin >> 6, c = lin & 63;
        int n = base + ln;
        hs[lin] = (n < NN) ? h[n * CC + c] : 0.f;
    }
    __syncthreads();
    int o = tid & 63, slot = tid >> 6;
#pragma unroll
    for (int rep = 0; rep < 4; rep++) {
        int ln = slot + rep * 4;
        int n = base + ln;
        if (n < NN) {
            float acc = 0.f;
#pragma unroll
            for (int c = 0; c < CC; c++) acc = fmaf(hs[ln * CC + c], Ws[c * CC + o], acc);
            d_hup[n * CC + o] = acc;
        }
    }
}

// Fused message + aggregation: block = node, thread = channel.
// agg[n,c,s] = (1/32) * sum_edges (z[e]·W_r2[:,c,s]) * h_up[snd,c] * sh[e,s]
__global__ __launch_bounds__(64) void k_agg(int t, const int* __restrict__ ei,
                                            const float* __restrict__ Wr2) {
    int n = blockIdx.x;
    int c = threadIdx.x;
    const float* __restrict__ z = d_z[t];
    float W[16][9];
#pragma unroll
    for (int m = 0; m < 16; m++)
#pragma unroll
        for (int s = 0; s < 9; s++) W[m][s] = Wr2[m * 576 + c * 9 + s];
    float acc[9];
#pragma unroll
    for (int s = 0; s < 9; s++) acc[s] = 0.f;
    int b = d_offs[n], e1 = d_offs[n + 1];
    for (int i = b; i < e1; i++) {
        int e = d_sorted[i];
        int snd = ei[e];
        float hv = d_hup[snd * CC + c];
        float zz[16];
#pragma unroll
        for (int m = 0; m < 16; m++) zz[m] = z[e * 16 + m];
        float ws[9];
#pragma unroll
        for (int s = 0; s < 9; s++) ws[s] = 0.f;
#pragma unroll
        for (int m = 0; m < 16; m++)
#pragma unroll
            for (int s = 0; s < 9; s++) ws[s] = fmaf(zz[m], W[m][s], ws[s]);
#pragma unroll
        for (int s = 0; s < 9; s++) acc[s] = fmaf(hv * d_sh[e * 9 + s], ws[s], acc[s]);
    }
#pragma unroll
    for (int s = 0; s < 9; s++) d_agg[n * 576 + c * 9 + s] = acc[s] * (1.0f / 32.0f);
}

// h' = [AGG | h] @ [W_mix ; W_self]   (M=N nodes, K=640, Nout=64)
__global__ __launch_bounds__(256) void k_update(int hsel, const float* __restrict__ Wmix,
                                                const float* __restrict__ Wself) {
    const float* __restrict__ h   = hsel ? d_hB : d_hA;
    float* __restrict__       out = hsel ? d_hA : d_hB;
    __shared__ __align__(16) float As[16][129];
    __shared__ __align__(16) float Bs[16][64];
    int tid = threadIdx.x;
    int tx = tid & 15, ty = tid >> 4;
    int nodeBase = blockIdx.x * 128;
    float acc[8][4];
#pragma unroll
    for (int i = 0; i < 8; i++)
#pragma unroll
        for (int j = 0; j < 4; j++) acc[i][j] = 0.f;

    for (int k0 = 0; k0 < 640; k0 += 16) {
#pragma unroll
        for (int i = 0; i < 8; i++) {
            int lin = tid + i * 256;
            int m = lin >> 4, k = lin & 15;
            int node = nodeBase + m;
            int kg = k0 + k;
            float v = 0.f;
            if (node < NN) v = (kg < 576) ? d_agg[node * 576 + kg] : h[node * CC + (kg - 576)];
            As[k][m] = v;
        }
#pragma unroll
        for (int i = 0; i < 4; i++) {
            int lin = tid + i * 256;
            int k = lin >> 6, o = lin & 63;
            int kg = k0 + k;
            Bs[k][o] = (kg < 576) ? Wmix[kg * 64 + o] : Wself[(kg - 576) * 64 + o];
        }
        __syncthreads();
#pragma unroll
        for (int k = 0; k < 16; k++) {
            float4 bv = *reinterpret_cast<const float4*>(&Bs[k][tx * 4]);
            float b0 = bv.x, b1 = bv.y, b2 = bv.z, b3 = bv.w;
            float a[8];
#pragma unroll
            for (int i = 0; i < 8; i++) a[i] = As[k][ty * 8 + i];
#pragma unroll
            for (int i = 0; i < 8; i++) {
                acc[i][0] = fmaf(a[i], b0, acc[i][0]);
                acc[i][1] = fmaf(a[i], b1, acc[i][1]);
                acc[i][2] = fmaf(a[i], b2, acc[i][2]);
                acc[i][3] = fmaf(a[i], b3, acc[i][3]);
            }
        }
        __syncthreads();
    }
#pragma unroll
    for (int i = 0; i < 8; i++) {
        int node = nodeBase + ty * 8 + i;
        if (node < NN) {
            float4 v = make_float4(acc[i][0], acc[i][1], acc[i][2], acc[i][3]);
            *reinterpret_cast<float4*>((hsel ? d_hA : d_hB) + node * CC + tx * 4) = v;
        }
    }
    (void)out;
}

// rep1 = h1 @ w_read   (h1 lives in d_hB)
__global__ void k_read1(const float* __restrict__ wr, float* __restrict__ out) {
    int gw = (blockIdx.x * blockDim.x + threadIdx.x) >> 5;
    int lane = threadIdx.x & 31;
    if (gw >= NN) return;
    const float* __restrict__ h = d_hB;
    float v = h[gw * 64 + lane] * wr[lane] + h[gw * 64 + 32 + lane] * wr[32 + lane];
#pragma unroll
    for (int o = 16; o; o >>= 1) v += __shfl_xor_sync(0xffffffffu, v, o);
    if (lane == 0) out[NN + gw] = v;
}

// rep2 = silu(h2 @ W_mlp1) @ w_mlp2   (h2 lives in d_hA)
__global__ void k_read2(const float* __restrict__ W1, const float* __restrict__ w2,
                        float* __restrict__ out) {
    int gw = (blockIdx.x * blockDim.x + threadIdx.x) >> 5;
    int lane = threadIdx.x & 31;
    if (gw >= NN) return;
    const float* __restrict__ h = d_hA;
    float v = 0.f;
    if (lane < 16) {
        float y = 0.f;
#pragma unroll
        for (int o = 0; o < 64; o++) y = fmaf(h[gw * 64 + o], W1[o * 16 + lane], y);
        float sy = y / (1.0f + expf(-y));
        v = sy * w2[lane];
    }
#pragma unroll
    for (int o = 16; o; o >>= 1) v += __shfl_xor_sync(0xffffffffu, v, o);
    if (lane == 0) out[2 * NN + gw] = v;
}

// ---------------- host launch ----------------
extern "C" void kernel_launch(void* const* d_in, const int* in_sizes, int n_in,
                              void* d_out, int out_size) {
    // Resolve inputs by unique element counts (robust to metadata ordering).
    const float *positions = nullptr, *node_attrs = nullptr, *shifts = nullptr;
    const float *atomic_energies = nullptr, *W_embed = nullptr, *W_up = nullptr;
    const float *W_r1 = nullptr, *W_r2 = nullptr, *W_mix = nullptr, *W_self = nullptr;
    const float *w_read = nullptr, *W_mlp1 = nullptr, *w_mlp2 = nullptr;
    const int* edge_index = nullptr;
    for (int i = 0; i < n_in; i++) {
        switch (in_sizes[i]) {
            case 30000:  positions = (const float*)d_in[i]; break;
            case 100000: node_attrs = (const float*)d_in[i]; break;
            case 480000: shifts = (const float*)d_in[i]; break;
            case 320000: edge_index = (const int*)d_in[i]; break;
            case 10:     atomic_energies = (const float*)d_in[i]; break;
            case 640:    W_embed = (const float*)d_in[i]; break;
            case 8192:   if (!W_up) W_up = (const float*)d_in[i];
                         else W_self = (const float*)d_in[i]; break;
            case 256:    W_r1 = (const float*)d_in[i]; break;
            case 18432:  W_r2 = (const float*)d_in[i]; break;
            case 73728:  W_mix = (const float*)d_in[i]; break;
            case 64:     w_read = (const float*)d_in[i]; break;
            case 1024:   W_mlp1 = (const float*)d_in[i]; break;
            case 16:     w_mlp2 = (const float*)d_in[i]; break;
            default: break;
        }
    }
    float* out = (float*)d_out;
    (void)out_size;

    k_zero_counts<<<(NN + 255) / 256, 256>>>();
    k_embed<<<NN, 64>>>(node_attrs, W_embed, atomic_energies, out);
    k_geom<<<(EE + 255) / 256, 256>>>(positions, shifts, edge_index, W_r1);
    k_scan<<<1, 1024>>>();
    k_scatter<<<(EE + 255) / 256, 256>>>(edge_index);

    const int readGrid = (NN * 32 + 255) / 256;
    for (int t = 0; t < 2; t++) {
        k_hup<<<(NN + 15) / 16, 256>>>(t, W_up + t * CC * CC);
        k_agg<<<NN, 64>>>(t, edge_index, W_r2 + t * 16 * 576);
        k_update<<<(NN + 127) / 128, 256>>>(t, W_mix + t * 576 * 64, W_self + t * CC * CC);
        if (t == 0) k_read1<<<readGrid, 256>>>(w_read, out);
        else        k_read2<<<readGrid, 256>>>(W_mlp1, w_mlp2, out);
    }
}

// round 2
// speedup vs baseline: 1.0393x; 1.0393x over previous
#include <cuda_runtime.h>
#include <math.h>

#define NN   10000
#define EE   160000
#define CC   64
#define SHD  9
#define SHP  12          // padded sh stride (float4-friendly)
#define RMAXF 5.0f
#define NPB  8           // nodes per block in k_agg

// ---------------- device scratch (static, allocation-free) ----------------
__device__ float d_sh[EE * SHP];
__device__ float d_z[2][EE * 16];
__device__ unsigned char d_act[EE];
__device__ int   d_count[NN];
__device__ int   d_offs[NN + 1];
__device__ int   d_cursor[NN];
__device__ int   d_sorted[EE];       // edge id per sorted slot
__device__ int   d_ssnd[EE];         // sender id per sorted slot
__device__ float d_hA[NN * CC];
__device__ float d_hB[NN * CC];
__device__ float d_hup[NN * CC];
__device__ float d_agg[NN * CC * SHD];

// ---------------- kernels ----------------
__global__ void k_zero_counts() {
    int i = blockIdx.x * blockDim.x + threadIdx.x;
    if (i < NN) d_count[i] = 0;
}

__global__ void k_embed(const float* __restrict__ na, const float* __restrict__ We,
                        const float* __restrict__ ae, float* __restrict__ out) {
    int n = blockIdx.x;
    int c = threadIdx.x;
    float acc = 0.f;
#pragma unroll
    for (int k = 0; k < 10; k++) acc = fmaf(na[n * 10 + k], We[k * CC + c], acc);
    d_hA[n * CC + c] = acc;
    if (c == 0) {
        float r = 0.f;
#pragma unroll
        for (int k = 0; k < 10; k++) r = fmaf(na[n * 10 + k], ae[k], r);
        out[n] = r;
    }
}

// Per-edge geometry: sh, radial, z[t][16]; histogram by rcv. W_r1 staged in smem.
__global__ __launch_bounds__(256) void k_geom(const float* __restrict__ pos,
                       const float* __restrict__ shifts,
                       const int* __restrict__ ei, const float* __restrict__ Wr1) {
    __shared__ float Ws[256];
    if (threadIdx.x < 256) Ws[threadIdx.x] = Wr1[threadIdx.x];
    __syncthreads();
    int e = blockIdx.x * blockDim.x + threadIdx.x;
    if (e >= EE) return;
    int s  = ei[e];
    int rv = ei[EE + e];
    float vx = pos[rv * 3 + 0] - pos[s * 3 + 0] + shifts[e * 3 + 0];
    float vy = pos[rv * 3 + 1] - pos[s * 3 + 1] + shifts[e * 3 + 1];
    float vz = pos[rv * 3 + 2] - pos[s * 3 + 2] + shifts[e * 3 + 2];
    float r = sqrtf(vx * vx + vy * vy + vz * vz) + 1e-9f;
    float xx = r * (1.0f / RMAXF);
    bool act = (xx < 1.0f);
    d_act[e] = act ? 1 : 0;
    if (!act) return;
    atomicAdd(&d_count[rv], 1);

    float inv = 1.0f / r;
    float ux = vx * inv, uy = vy * inv, uz = vz * inv;
    const float s3 = 1.7320508075688772f, s5 = 2.2360679774997896f, s15 = 3.872983346207417f;
    float4 shA = make_float4(1.0f, s3 * ux, s3 * uy, s3 * uz);
    float4 shB = make_float4(s15 * ux * uy, s15 * uy * uz,
                             0.5f * s5 * (3.0f * uz * uz - 1.0f), s15 * ux * uz);
    float sh8 = 0.5f * s15 * (ux * ux - uy * uy);
    *reinterpret_cast<float4*>(&d_sh[e * SHP + 0]) = shA;
    *reinterpret_cast<float4*>(&d_sh[e * SHP + 4]) = shB;
    d_sh[e * SHP + 8] = sh8;

    float th = 3.14159265358979323846f * xx;
    float s1, c1;
    sincosf(th, &s1, &c1);
    float x2 = xx * xx;
    float x6 = x2 * x2 * x2;
    float fc = 1.0f + x6 * (-28.0f + xx * (48.0f - 21.0f * xx));
    float pref = 0.6324555320336759f * inv * fc;
    float ef[8];
    float sp = 0.0f, sc = s1, c2 = 2.0f * c1;
#pragma unroll
    for (int n = 0; n < 8; n++) {
        ef[n] = pref * sc;
        float nx = c2 * sc - sp;
        sp = sc; sc = nx;
    }
#pragma unroll
    for (int t = 0; t < 2; t++) {
#pragma unroll
        for (int m = 0; m < 16; m++) {
            float a = 0.f;
#pragma unroll
            for (int n = 0; n < 8; n++) a = fmaf(ef[n], Ws[t * 128 + n * 16 + m], a);
            d_z[t][e * 16 + m] = a / (1.0f + expf(-a));
        }
    }
}

// Exclusive scan over d_count via warp shuffles (single block, 1024 threads).
__global__ __launch_bounds__(1024) void k_scan() {
    const int CH = 10;                 // 1024 * 10 >= NN
    __shared__ int wsum[32];
    int t = threadIdx.x;
    int lane = t & 31, warp = t >> 5;
    int base = t * CH;
    int v[CH];
#pragma unroll
    for (int i = 0; i < CH; i++) {
        int idx = base + i;
        v[i] = (idx < NN) ? d_count[idx] : 0;
    }
    int s = 0;
#pragma unroll
    for (int i = 0; i < CH; i++) s += v[i];
    // warp inclusive scan of s
    int inc = s;
#pragma unroll
    for (int o = 1; o < 32; o <<= 1) {
        int u = __shfl_up_sync(0xffffffffu, inc, o);
        if (lane >= o) inc += u;
    }
    if (lane == 31) wsum[warp] = inc;
    __syncthreads();
    if (warp == 0) {
        int w = wsum[lane];
        int wi = w;
#pragma unroll
        for (int o = 1; o < 32; o <<= 1) {
            int u = __shfl_up_sync(0xffffffffu, wi, o);
            if (lane >= o) wi += u;
        }
        wsum[lane] = wi - w;   // exclusive
    }
    __syncthreads();
    int run = wsum[warp] + inc - s;    // exclusive prefix for this thread
#pragma unroll
    for (int i = 0; i < CH; i++) {
        int idx = base + i;
        if (idx < NN) { d_offs[idx] = run; d_cursor[idx] = run; run += v[i]; }
    }
    if (t == 1023) d_offs[NN] = run;
}

__global__ void k_scatter(const int* __restrict__ ei) {
    int e = blockIdx.x * blockDim.x + threadIdx.x;
    if (e >= EE) return;
    if (!d_act[e]) return;
    int rv = ei[EE + e];
    int p = atomicAdd(&d_cursor[rv], 1);
    d_sorted[p] = e;
    d_ssnd[p] = ei[e];
}

// h_up = h @ W_up[t]
__global__ __launch_bounds__(256) void k_hup(int hsel, const float* __restrict__ Wup) {
    const float* __restrict__ h = hsel ? d_hB : d_hA;
    __shared__ float Ws[CC * CC];
    __shared__ float hs[16 * CC];
    int tid = threadIdx.x;
    int base = blockIdx.x * 16;
#pragma unroll
    for (int i = 0; i < 16; i++) Ws[tid + i * 256] = Wup[tid + i * 256];
#pragma unroll
    for (int i = 0; i < 4; i++) {
        int lin = tid + i * 256;
        int ln = lin >> 6, c = lin & 63;
        int n = base + ln;
        hs[lin] = (n < NN) ? h[n * CC + c] : 0.f;
    }
    __syncthreads();
    int o = tid & 63, slot = tid >> 6;
#pragma unroll
    for (int rep = 0; rep < 4; rep++) {
        int ln = slot + rep * 4;
        int n = base + ln;
        if (n < NN) {
            float acc = 0.f;
#pragma unroll
            for (int c = 0; c < CC; c++) acc = fmaf(hs[ln * CC + c], Ws[c * CC + o], acc);
            d_hup[n * CC + o] = acc;
        }
    }
}

// Fused message + aggregation. Block = 64 threads (channels) x NPB nodes.
// W_r2 slice kept in registers across all NPB nodes.
__global__ __launch_bounds__(64) void k_agg(int t, const float* __restrict__ Wr2) {
    int c = threadIdx.x;
    const float* __restrict__ z = d_z[t];
    float W[16][9];
#pragma unroll
    for (int m = 0; m < 16; m++)
#pragma unroll
        for (int s = 0; s < 9; s++) W[m][s] = Wr2[m * 576 + c * 9 + s];

    int n0 = blockIdx.x * NPB;
    int n1 = n0 + NPB;
    if (n1 > NN) n1 = NN;
    for (int n = n0; n < n1; n++) {
        float acc[9];
#pragma unroll
        for (int s = 0; s < 9; s++) acc[s] = 0.f;
        int b = d_offs[n], e1 = d_offs[n + 1];
        for (int i = b; i < e1; i++) {
            int e   = d_sorted[i];
            int snd = d_ssnd[i];
            float hv = d_hup[snd * CC + c];
            const float4* z4 = reinterpret_cast<const float4*>(&z[e * 16]);
            float4 za = z4[0], zb = z4[1], zc = z4[2], zd = z4[3];
            float zz[16] = {za.x, za.y, za.z, za.w, zb.x, zb.y, zb.z, zb.w,
                            zc.x, zc.y, zc.z, zc.w, zd.x, zd.y, zd.z, zd.w};
            float4 sA = *reinterpret_cast<const float4*>(&d_sh[e * SHP + 0]);
            float4 sB = *reinterpret_cast<const float4*>(&d_sh[e * SHP + 4]);
            float sh8 = d_sh[e * SHP + 8];
            float shv[9] = {sA.x, sA.y, sA.z, sA.w, sB.x, sB.y, sB.z, sB.w, sh8};
            float ws[9];
#pragma unroll
            for (int s = 0; s < 9; s++) ws[s] = 0.f;
#pragma unroll
            for (int m = 0; m < 16; m++)
#pragma unroll
                for (int s = 0; s < 9; s++) ws[s] = fmaf(zz[m], W[m][s], ws[s]);
#pragma unroll
            for (int s = 0; s < 9; s++) acc[s] = fmaf(hv * shv[s], ws[s], acc[s]);
        }
#pragma unroll
        for (int s = 0; s < 9; s++) d_agg[n * 576 + c * 9 + s] = acc[s] * (1.0f / 32.0f);
    }
}

// h' = [AGG | h] @ [W_mix ; W_self]
__global__ __launch_bounds__(256) void k_update(int hsel, const float* __restrict__ Wmix,
                                                const float* __restrict__ Wself) {
    const float* __restrict__ h = hsel ? d_hB : d_hA;
    __shared__ __align__(16) float As[16][129];
    __shared__ __align__(16) float Bs[16][64];
    int tid = threadIdx.x;
    int tx = tid & 15, ty = tid >> 4;
    int nodeBase = blockIdx.x * 128;
    float acc[8][4];
#pragma unroll
    for (int i = 0; i < 8; i++)
#pragma unroll
        for (int j = 0; j < 4; j++) acc[i][j] = 0.f;

    for (int k0 = 0; k0 < 640; k0 += 16) {
#pragma unroll
        for (int i = 0; i < 8; i++) {
            int lin = tid + i * 256;
            int m = lin >> 4, k = lin & 15;
            int node = nodeBase + m;
            int kg = k0 + k;
            float v = 0.f;
            if (node < NN) v = (kg < 576) ? d_agg[node * 576 + kg] : h[node * CC + (kg - 576)];
            As[k][m] = v;
        }
#pragma unroll
        for (int i = 0; i < 4; i++) {
            int lin = tid + i * 256;
            int k = lin >> 6, o = lin & 63;
            int kg = k0 + k;
            Bs[k][o] = (kg < 576) ? Wmix[kg * 64 + o] : Wself[(kg - 576) * 64 + o];
        }
        __syncthreads();
#pragma unroll
        for (int k = 0; k < 16; k++) {
            float4 bv = *reinterpret_cast<const float4*>(&Bs[k][tx * 4]);
            float a[8];
#pragma unroll
            for (int i = 0; i < 8; i++) a[i] = As[k][ty * 8 + i];
#pragma unroll
            for (int i = 0; i < 8; i++) {
                acc[i][0] = fmaf(a[i], bv.x, acc[i][0]);
                acc[i][1] = fmaf(a[i], bv.y, acc[i][1]);
                acc[i][2] = fmaf(a[i], bv.z, acc[i][2]);
                acc[i][3] = fmaf(a[i], bv.w, acc[i][3]);
            }
        }
        __syncthreads();
    }
    float* outp = hsel ? d_hA : d_hB;
#pragma unroll
    for (int i = 0; i < 8; i++) {
        int node = nodeBase + ty * 8 + i;
        if (node < NN) {
            float4 v = make_float4(acc[i][0], acc[i][1], acc[i][2], acc[i][3]);
            *reinterpret_cast<float4*>(outp + node * CC + tx * 4) = v;
        }
    }
}

__global__ void k_read1(const float* __restrict__ wr, float* __restrict__ out) {
    int gw = (blockIdx.x * blockDim.x + threadIdx.x) >> 5;
    int lane = threadIdx.x & 31;
    if (gw >= NN) return;
    const float* __restrict__ h = d_hB;
    float v = h[gw * 64 + lane] * wr[lane] + h[gw * 64 + 32 + lane] * wr[32 + lane];
#pragma unroll
    for (int o = 16; o; o >>= 1) v += __shfl_xor_sync(0xffffffffu, v, o);
    if (lane == 0) out[NN + gw] = v;
}

__global__ void k_read2(const float* __restrict__ W1, const float* __restrict__ w2,
                        float* __restrict__ out) {
    int gw = (blockIdx.x * blockDim.x + threadIdx.x) >> 5;
    int lane = threadIdx.x & 31;
    if (gw >= NN) return;
    const float* __restrict__ h = d_hA;
    float v = 0.f;
    if (lane < 16) {
        float y = 0.f;
#pragma unroll
        for (int o = 0; o < 64; o++) y = fmaf(h[gw * 64 + o], W1[o * 16 + lane], y);
        float sy = y / (1.0f + expf(-y));
        v = sy * w2[lane];
    }
#pragma unroll
    for (int o = 16; o; o >>= 1) v += __shfl_xor_sync(0xffffffffu, v, o);
    if (lane == 0) out[2 * NN + gw] = v;
}

// ---------------- host launch ----------------
extern "C" void kernel_launch(void* const* d_in, const int* in_sizes, int n_in,
                              void* d_out, int out_size) {
    const float *positions = nullptr, *node_attrs = nullptr, *shifts = nullptr;
    const float *atomic_energies = nullptr, *W_embed = nullptr, *W_up = nullptr;
    const float *W_r1 = nullptr, *W_r2 = nullptr, *W_mix = nullptr, *W_self = nullptr;
    const float *w_read = nullptr, *W_mlp1 = nullptr, *w_mlp2 = nullptr;
    const int* edge_index = nullptr;
    for (int i = 0; i < n_in; i++) {
        switch (in_sizes[i]) {
            case 30000:  positions = (const float*)d_in[i]; break;
            case 100000: node_attrs = (const float*)d_in[i]; break;
            case 480000: shifts = (const float*)d_in[i]; break;
            case 320000: edge_index = (const int*)d_in[i]; break;
            case 10:     atomic_energies = (const float*)d_in[i]; break;
            case 640:    W_embed = (const float*)d_in[i]; break;
            case 8192:   if (!W_up) W_up = (const float*)d_in[i];
                         else W_self = (const float*)d_in[i]; break;
            case 256:    W_r1 = (const float*)d_in[i]; break;
            case 18432:  W_r2 = (const float*)d_in[i]; break;
            case 73728:  W_mix = (const float*)d_in[i]; break;
            case 64:     w_read = (const float*)d_in[i]; break;
            case 1024:   W_mlp1 = (const float*)d_in[i]; break;
            case 16:     w_mlp2 = (const float*)d_in[i]; break;
            default: break;
        }
    }
    float* out = (float*)d_out;
    (void)out_size;

    k_zero_counts<<<(NN + 255) / 256, 256>>>();
    k_embed<<<NN, 64>>>(node_attrs, W_embed, atomic_energies, out);
    k_geom<<<(EE + 255) / 256, 256>>>(positions, shifts, edge_index, W_r1);
    k_scan<<<1, 1024>>>();
    k_scatter<<<(EE + 255) / 256, 256>>>(edge_index);

    const int readGrid = (NN * 32 + 255) / 256;
    for (int t = 0; t < 2; t++) {
        k_hup<<<(NN + 15) / 16, 256>>>(t, W_up + t * CC * CC);
        k_agg<<<(NN + NPB - 1) / NPB, 64>>>(t, W_r2 + t * 16 * 576);
        k_update<<<(NN + 127) / 128, 256>>>(t, W_mix + t * 576 * 64, W_self + t * CC * CC);
        if (t == 0) k_read1<<<readGrid, 256>>>(w_read, out);
        else        k_read2<<<readGrid, 256>>>(W_mlp1, w_mlp2, out);
    }
}

// round 3
// speedup vs baseline: 1.7030x; 1.6385x over previous
#include <cuda_runtime.h>
#include <math.h>

#define NN   10000
#define EE   160000
#define CC   64
#define SHP  16          // padded sh stride
#define RMAXF 5.0f
#define NPB  16          // nodes per block in k_agg

// ---------------- device scratch ----------------
__device__ float d_sh[EE * SHP];
__device__ float d_z[2][EE * 16];
__device__ unsigned char d_act[EE];
__device__ int   d_count[NN];
__device__ int   d_offs[NN + 1];
__device__ int   d_cursor[NN];
__device__ int2  d_sedge[EE];        // (edge id, sender id) per sorted slot
__device__ int   d_bsum[16];
__device__ float d_hA[NN * CC];      // h0
__device__ float d_hB[NN * CC];      // h1 (atomic accum)
__device__ float d_hC[NN * CC];      // h2 (atomic accum)
__device__ float d_hup[NN * CC];
__device__ float d_agg[NN * CC * 9];

// ---------------- kernels ----------------
__global__ void k_zero() {
    int i = blockIdx.x * blockDim.x + threadIdx.x;
    float4 z = make_float4(0.f, 0.f, 0.f, 0.f);
    if (i * 4 < NN * CC) {
        *reinterpret_cast<float4*>(d_hB + i * 4) = z;
        *reinterpret_cast<float4*>(d_hC + i * 4) = z;
    }
}

__global__ void k_embed(const float* __restrict__ na, const float* __restrict__ We,
                        const float* __restrict__ ae, float* __restrict__ out) {
    int n = blockIdx.x;
    int c = threadIdx.x;
    float acc = 0.f;
#pragma unroll
    for (int k = 0; k < 10; k++) acc = fmaf(na[n * 10 + k], We[k * CC + c], acc);
    d_hA[n * CC + c] = acc;
    if (c == 0) {
        d_count[n] = 0;
        float r = 0.f;
#pragma unroll
        for (int k = 0; k < 10; k++) r = fmaf(na[n * 10 + k], ae[k], r);
        out[n] = r;
    }
}

__global__ __launch_bounds__(256) void k_geom(const float* __restrict__ pos,
                       const float* __restrict__ shifts,
                       const int* __restrict__ ei, const float* __restrict__ Wr1) {
    __shared__ float Ws[256];
    Ws[threadIdx.x] = Wr1[threadIdx.x];
    __syncthreads();
    int e = blockIdx.x * blockDim.x + threadIdx.x;
    if (e >= EE) return;
    int s  = ei[e];
    int rv = ei[EE + e];
    float vx = pos[rv * 3 + 0] - pos[s * 3 + 0] + shifts[e * 3 + 0];
    float vy = pos[rv * 3 + 1] - pos[s * 3 + 1] + shifts[e * 3 + 1];
    float vz = pos[rv * 3 + 2] - pos[s * 3 + 2] + shifts[e * 3 + 2];
    float r = sqrtf(vx * vx + vy * vy + vz * vz) + 1e-9f;
    float xx = r * (1.0f / RMAXF);
    bool act = (xx < 1.0f);
    d_act[e] = act ? 1 : 0;
    if (!act) return;
    atomicAdd(&d_count[rv], 1);

    float inv = __fdividef(1.0f, r);
    float ux = vx * inv, uy = vy * inv, uz = vz * inv;
    const float s3 = 1.7320508075688772f, s5 = 2.2360679774997896f, s15 = 3.872983346207417f;
    // layout: [0..3]=sh0..3, [4]=sh4, [8..11]=sh5..8
    float4 shA = make_float4(1.0f, s3 * ux, s3 * uy, s3 * uz);
    float sh4 = s15 * ux * uy;
    float4 shB = make_float4(s15 * uy * uz, 0.5f * s5 * (3.0f * uz * uz - 1.0f),
                             s15 * ux * uz, 0.5f * s15 * (ux * ux - uy * uy));
    *reinterpret_cast<float4*>(&d_sh[e * SHP + 0]) = shA;
    d_sh[e * SHP + 4] = sh4;
    *reinterpret_cast<float4*>(&d_sh[e * SHP + 8]) = shB;

    float th = 3.14159265358979323846f * xx;
    float s1, c1;
    __sincosf(th, &s1, &c1);
    float x2 = xx * xx;
    float x6 = x2 * x2 * x2;
    float fc = 1.0f + x6 * (-28.0f + xx * (48.0f - 21.0f * xx));
    float pref = 0.6324555320336759f * inv * fc;
    float ef[8];
    float sp = 0.0f, sc = s1, c2 = 2.0f * c1;
#pragma unroll
    for (int n = 0; n < 8; n++) {
        ef[n] = pref * sc;
        float nx = c2 * sc - sp;
        sp = sc; sc = nx;
    }
#pragma unroll
    for (int t = 0; t < 2; t++) {
        float a[16];
#pragma unroll
        for (int m = 0; m < 16; m++) {
            float acc = 0.f;
#pragma unroll
            for (int n = 0; n < 8; n++) acc = fmaf(ef[n], Ws[t * 128 + n * 16 + m], acc);
            a[m] = __fdividef(acc, 1.0f + __expf(-acc));   // fast silu
        }
        float* dst = &d_z[t][e * 16];
#pragma unroll
        for (int q = 0; q < 4; q++)
            *reinterpret_cast<float4*>(dst + q * 4) =
                make_float4(a[q * 4], a[q * 4 + 1], a[q * 4 + 2], a[q * 4 + 3]);
    }
}

// two-kernel coalesced scan
__global__ __launch_bounds__(1024) void k_scan1() {
    __shared__ int ws[32];
    int t = threadIdx.x, lane = t & 31, w = t >> 5;
    int idx = blockIdx.x * 1024 + t;
    int v = (idx < NN) ? d_count[idx] : 0;
    int inc = v;
#pragma unroll
    for (int o = 1; o < 32; o <<= 1) {
        int u = __shfl_up_sync(0xffffffffu, inc, o);
        if (lane >= o) inc += u;
    }
    if (lane == 31) ws[w] = inc;
    __syncthreads();
    if (w == 0) {
        int x = ws[lane];
        int xi = x;
#pragma unroll
        for (int o = 1; o < 32; o <<= 1) {
            int u = __shfl_up_sync(0xffffffffu, xi, o);
            if (lane >= o) xi += u;
        }
        ws[lane] = xi - x;
    }
    __syncthreads();
    int excl = ws[w] + inc - v;
    if (idx < NN) d_offs[idx] = excl;
    if (t == 1023) d_bsum[blockIdx.x] = excl + v;
}

__global__ __launch_bounds__(1024) void k_scan2() {
    __shared__ int bp[11];
    if (threadIdx.x == 0) {
        int s = 0;
#pragma unroll
        for (int b = 0; b < 10; b++) { bp[b] = s; s += d_bsum[b]; }
        d_offs[NN] = s;
    }
    __syncthreads();
    for (int idx = threadIdx.x; idx < NN; idx += 1024) {
        int o = d_offs[idx] + bp[idx >> 10];
        d_offs[idx] = o;
        d_cursor[idx] = o;
    }
}

__global__ void k_scatter(const int* __restrict__ ei) {
    int e = blockIdx.x * blockDim.x + threadIdx.x;
    if (e >= EE) return;
    if (!d_act[e]) return;
    int rv = ei[EE + e];
    int p = atomicAdd(&d_cursor[rv], 1);
    d_sedge[p] = make_int2(e, ei[e]);
}

__global__ __launch_bounds__(256) void k_hup(int t, const float* __restrict__ Wup) {
    const float* __restrict__ h = t ? d_hB : d_hA;
    __shared__ float Ws[CC * CC];
    __shared__ float hs[16 * CC];
    int tid = threadIdx.x;
    int base = blockIdx.x * 16;
#pragma unroll
    for (int i = 0; i < 16; i++) Ws[tid + i * 256] = Wup[tid + i * 256];
#pragma unroll
    for (int i = 0; i < 4; i++) {
        int lin = tid + i * 256;
        int ln = lin >> 6, c = lin & 63;
        int n = base + ln;
        hs[lin] = (n < NN) ? h[n * CC + c] : 0.f;
    }
    __syncthreads();
    int o = tid & 63, slot = tid >> 6;
#pragma unroll
    for (int rep = 0; rep < 4; rep++) {
        int ln = slot + rep * 4;
        int n = base + ln;
        if (n < NN) {
            float acc = 0.f;
#pragma unroll
            for (int c = 0; c < CC; c++) acc = fmaf(hs[ln * CC + c], Ws[c * CC + o], acc);
            d_hup[n * CC + o] = acc;
        }
    }
}

// Fused message + aggregation. 128 threads = 64 channels x 2 sh-halves.
template<int SOFF, int SCNT>
__device__ __forceinline__ void agg_body(int c, int n0, int n1,
                                         const float* __restrict__ z,
                                         const float* __restrict__ Wr2) {
    float W[16][SCNT];
#pragma unroll
    for (int m = 0; m < 16; m++)
#pragma unroll
        for (int j = 0; j < SCNT; j++) W[m][j] = Wr2[m * 576 + c * 9 + SOFF + j];
    for (int n = n0; n < n1; n++) {
        float acc[SCNT];
#pragma unroll
        for (int j = 0; j < SCNT; j++) acc[j] = 0.f;
        int b = d_offs[n], e1 = d_offs[n + 1];
        for (int i = b; i < e1; i++) {
            int2 es = d_sedge[i];
            int e = es.x;
            float hv = d_hup[es.y * CC + c];
            const float4* z4 = reinterpret_cast<const float4*>(&z[e * 16]);
            float4 za = z4[0], zb = z4[1], zc = z4[2], zd = z4[3];
            float zz[16] = {za.x, za.y, za.z, za.w, zb.x, zb.y, zb.z, zb.w,
                            zc.x, zc.y, zc.z, zc.w, zd.x, zd.y, zd.z, zd.w};
            float shv[SCNT];
            if (SOFF == 0) {
                float4 sA = *reinterpret_cast<const float4*>(&d_sh[e * SHP]);
                shv[0] = sA.x; shv[1] = sA.y; shv[2] = sA.z; shv[3] = sA.w;
                if (SCNT > 4) shv[4] = d_sh[e * SHP + 4];
            } else {
                float4 sB = *reinterpret_cast<const float4*>(&d_sh[e * SHP + 8]);
                shv[0] = sB.x; shv[1] = sB.y; shv[2] = sB.z;
                if (SCNT > 3) shv[3] = sB.w;
            }
            float ws[SCNT];
#pragma unroll
            for (int j = 0; j < SCNT; j++) ws[j] = 0.f;
#pragma unroll
            for (int m = 0; m < 16; m++)
#pragma unroll
                for (int j = 0; j < SCNT; j++) ws[j] = fmaf(zz[m], W[m][j], ws[j]);
#pragma unroll
            for (int j = 0; j < SCNT; j++) acc[j] = fmaf(hv * shv[j], ws[j], acc[j]);
        }
#pragma unroll
        for (int j = 0; j < SCNT; j++)
            d_agg[n * 576 + c * 9 + SOFF + j] = acc[j] * (1.0f / 32.0f);
    }
}

__global__ __launch_bounds__(128) void k_agg(int t, const float* __restrict__ Wr2) {
    int c = threadIdx.x & 63;
    int half = threadIdx.x >> 6;
    int n0 = blockIdx.x * NPB;
    int n1 = n0 + NPB; if (n1 > NN) n1 = NN;
    const float* z = d_z[t];
    if (half == 0) agg_body<0, 5>(c, n0, n1, z, Wr2);
    else           agg_body<5, 4>(c, n0, n1, z, Wr2);
}

// h' += [AGG | h] @ [W_mix ; W_self], M=64 tile, K split 4x160, 8x8 per-thread.
__global__ __launch_bounds__(64) void k_update(int t, const float* __restrict__ Wmix,
                                               const float* __restrict__ Wself) {
    const float* __restrict__ h = t ? d_hB : d_hA;
    float* __restrict__ outp    = t ? d_hC : d_hB;
    __shared__ float As[16][64];
    __shared__ float Bs[16][64];
    int tid = threadIdx.x;
    int tx = tid & 7, ty = tid >> 3;
    int m0 = blockIdx.x * 64;
    int k0c = blockIdx.y * 160;
    float acc[8][8];
#pragma unroll
    for (int i = 0; i < 8; i++)
#pragma unroll
        for (int j = 0; j < 8; j++) acc[i][j] = 0.f;

    for (int kt = 0; kt < 160; kt += 16) {
        int k0 = k0c + kt;
        {   // As: thread <-> node, 16 consecutive k
            int node = m0 + tid;
            float4 va[4];
            if (node < NN) {
                const float* src = (k0 < 576) ? (d_agg + node * 576 + k0)
                                              : (h + node * CC + (k0 - 576));
#pragma unroll
                for (int j = 0; j < 4; j++) va[j] = *reinterpret_cast<const float4*>(src + 4 * j);
            } else {
#pragma unroll
                for (int j = 0; j < 4; j++) va[j] = make_float4(0.f, 0.f, 0.f, 0.f);
            }
#pragma unroll
            for (int j = 0; j < 4; j++) {
                As[4 * j + 0][tid] = va[j].x;
                As[4 * j + 1][tid] = va[j].y;
                As[4 * j + 2][tid] = va[j].z;
                As[4 * j + 3][tid] = va[j].w;
            }
        }
        {   // Bs: 256 float4s total, 4 per thread
#pragma unroll
            for (int j = 0; j < 4; j++) {
                int L = tid + 64 * j;
                int k = L >> 4, q = L & 15;
                int kg = k0 + k;
                const float* bsrc = (kg < 576) ? (Wmix + kg * 64) : (Wself + (kg - 576) * 64);
                *reinterpret_cast<float4*>(&Bs[k][q * 4]) =
                    *reinterpret_cast<const float4*>(bsrc + q * 4);
            }
        }
        __syncthreads();
#pragma unroll
        for (int k = 0; k < 16; k++) {
            float a[8], bb[8];
            *reinterpret_cast<float4*>(&a[0]) = *reinterpret_cast<const float4*>(&As[k][ty * 8]);
            *reinterpret_cast<float4*>(&a[4]) = *reinterpret_cast<const float4*>(&As[k][ty * 8 + 4]);
            *reinterpret_cast<float4*>(&bb[0]) = *reinterpret_cast<const float4*>(&Bs[k][tx * 8]);
            *reinterpret_cast<float4*>(&bb[4]) = *reinterpret_cast<const float4*>(&Bs[k][tx * 8 + 4]);
#pragma unroll
            for (int i = 0; i < 8; i++)
#pragma unroll
                for (int j = 0; j < 8; j++) acc[i][j] = fmaf(a[i], bb[j], acc[i][j]);
        }
        __syncthreads();
    }
#pragma unroll
    for (int i = 0; i < 8; i++) {
        int node = m0 + ty * 8 + i;
        if (node < NN) {
#pragma unroll
            for (int j = 0; j < 8; j++)
                atomicAdd(&outp[node * CC + tx * 8 + j], acc[i][j]);
        }
    }
}

__global__ void k_read1(const float* __restrict__ wr, float* __restrict__ out) {
    int gw = (blockIdx.x * blockDim.x + threadIdx.x) >> 5;
    int lane = threadIdx.x & 31;
    if (gw >= NN) return;
    const float* __restrict__ h = d_hB;
    float v = h[gw * 64 + lane] * wr[lane] + h[gw * 64 + 32 + lane] * wr[32 + lane];
#pragma unroll
    for (int o = 16; o; o >>= 1) v += __shfl_xor_sync(0xffffffffu, v, o);
    if (lane == 0) out[NN + gw] = v;
}

__global__ void k_read2(const float* __restrict__ W1, const float* __restrict__ w2,
                        float* __restrict__ out) {
    int gw = (blockIdx.x * blockDim.x + threadIdx.x) >> 5;
    int lane = threadIdx.x & 31;
    if (gw >= NN) return;
    const float* __restrict__ h = d_hC;
    float v = 0.f;
    if (lane < 16) {
        float y = 0.f;
#pragma unroll
        for (int o = 0; o < 64; o++) y = fmaf(h[gw * 64 + o], W1[o * 16 + lane], y);
        float sy = __fdividef(y, 1.0f + __expf(-y));
        v = sy * w2[lane];
    }
#pragma unroll
    for (int o = 16; o; o >>= 1) v += __shfl_xor_sync(0xffffffffu, v, o);
    if (lane == 0) out[2 * NN + gw] = v;
}

// ---------------- host launch ----------------
extern "C" void kernel_launch(void* const* d_in, const int* in_sizes, int n_in,
                              void* d_out, int out_size) {
    const float *positions = nullptr, *node_attrs = nullptr, *shifts = nullptr;
    const float *atomic_energies = nullptr, *W_embed = nullptr, *W_up = nullptr;
    const float *W_r1 = nullptr, *W_r2 = nullptr, *W_mix = nullptr, *W_self = nullptr;
    const float *w_read = nullptr, *W_mlp1 = nullptr, *w_mlp2 = nullptr;
    const int* edge_index = nullptr;
    for (int i = 0; i < n_in; i++) {
        switch (in_sizes[i]) {
            case 30000:  positions = (const float*)d_in[i]; break;
            case 100000: node_attrs = (const float*)d_in[i]; break;
            case 480000: shifts = (const float*)d_in[i]; break;
            case 320000: edge_index = (const int*)d_in[i]; break;
            case 10:     atomic_energies = (const float*)d_in[i]; break;
            case 640:    W_embed = (const float*)d_in[i]; break;
            case 8192:   if (!W_up) W_up = (const float*)d_in[i];
                         else W_self = (const float*)d_in[i]; break;
            case 256:    W_r1 = (const float*)d_in[i]; break;
            case 18432:  W_r2 = (const float*)d_in[i]; break;
            case 73728:  W_mix = (const float*)d_in[i]; break;
            case 64:     w_read = (const float*)d_in[i]; break;
            case 1024:   W_mlp1 = (const float*)d_in[i]; break;
            case 16:     w_mlp2 = (const float*)d_in[i]; break;
            default: break;
        }
    }
    float* out = (float*)d_out;
    (void)out_size;

    k_zero<<<(NN * CC / 4 + 255) / 256, 256>>>();
    k_embed<<<NN, 64>>>(node_attrs, W_embed, atomic_energies, out);
    k_geom<<<(EE + 255) / 256, 256>>>(positions, shifts, edge_index, W_r1);
    k_scan1<<<10, 1024>>>();
    k_scan2<<<1, 1024>>>();
    k_scatter<<<(EE + 255) / 256, 256>>>(edge_index);

    const int readGrid = (NN * 32 + 255) / 256;
    dim3 ugrid((NN + 63) / 64, 4);
    for (int t = 0; t < 2; t++) {
        k_hup<<<(NN + 15) / 16, 256>>>(t, W_up + t * CC * CC);
        k_agg<<<(NN + NPB - 1) / NPB, 128>>>(t, W_r2 + t * 16 * 576);
        k_update<<<ugrid, 64>>>(t, W_mix + t * 576 * 64, W_self + t * CC * CC);
        if (t == 0) k_read1<<<readGrid, 256>>>(w_read, out);
        else        k_read2<<<readGrid, 256>>>(W_mlp1, w_mlp2, out);
    }
}